// round 7
// baseline (speedup 1.0000x reference)
#include <cuda_runtime.h>
#include <cuda_bf16.h>

// PairwiseDistances: d[e] = || R[idx_i[e]] - R[idx_j[e]] ||_2
// R: [N,3] f32 (N=100000); idx: int32 [E]; out: f32 [E]. E = 6,400,000.
//
// R6 evidence: L1tex wavefront-floor-bound (83.2% L1, 2.09 wf/edge ≈ 50 us).
// R7: (a) serve gathers with idx < 12800 from a 200 KB SMEM slice (LDS
// crossbar ~4-8x cheaper per random gather than LDG wavefronts), persistent
// grid so the slice loads once per SM; (b) vectorized pad prologue.

#define R4_CAP     131072        // padded table capacity (2 MB)
#define SMEM_ATOMS 12800         // 200 KB float4 slice cached in SMEM

__device__ float4 g_R4[R4_CAP];

// ---------- prologue: pad R[N,3] -> g_R4[N] (float4), vectorized ----------
// 4 atoms (48B = 3 float4 reads) per thread -> 4 float4 writes.
__global__ __launch_bounds__(256) void pad_R_kernel(
    const float4* __restrict__ R4in, int n_groups /* ceil(n/4) */, int n_atoms)
{
    int g = blockIdx.x * blockDim.x + threadIdx.x;
    if (g >= n_groups) return;
    int base = g * 4;
    if (base + 4 <= n_atoms) {
        float4 p0 = __ldg(R4in + 3*g + 0);   // x0 y0 z0 x1
        float4 p1 = __ldg(R4in + 3*g + 1);   // y1 z1 x2 y2
        float4 p2 = __ldg(R4in + 3*g + 2);   // z2 x3 y3 z3
        g_R4[base + 0] = make_float4(p0.x, p0.y, p0.z, 0.f);
        g_R4[base + 1] = make_float4(p0.w, p1.x, p1.y, 0.f);
        g_R4[base + 2] = make_float4(p1.z, p1.w, p2.x, 0.f);
        g_R4[base + 3] = make_float4(p2.y, p2.z, p2.w, 0.f);
    } else {
        const float* r = (const float*)R4in;
        for (int a = base; a < n_atoms; ++a)
            g_R4[a] = make_float4(r[3*a+0], r[3*a+1], r[3*a+2], 0.f);
    }
}

// ---------- gather helpers ----------
__device__ __forceinline__ float4 ldg_row(int idx)
{
    float4 v;
    const float4* p = g_R4 + (unsigned)idx;
    asm("ld.global.nc.L1::evict_last.v4.f32 {%0,%1,%2,%3}, [%4];"
        : "=f"(v.x), "=f"(v.y), "=f"(v.z), "=f"(v.w)
        : "l"(p));
    return v;
}

__device__ __forceinline__ float4 fetch(const float4* __restrict__ sm, int idx)
{
    return (idx < SMEM_ATOMS) ? sm[idx] : ldg_row(idx);
}

// ---------- main kernel: persistent grid, SMEM-hybrid gathers ----------
__global__ __launch_bounds__(1024, 1) void pairwise_dist_hybrid_kernel(
    const int* __restrict__ idx_i,
    const int* __restrict__ idx_j,
    float* __restrict__ out,
    int num_quads)   // E/4
{
    extern __shared__ float4 sm[];
    // Cooperative load of the SMEM slice (coalesced 16B from padded table).
    for (int a = threadIdx.x; a < SMEM_ATOMS; a += blockDim.x)
        sm[a] = g_R4[a];
    __syncthreads();

    int stride = gridDim.x * blockDim.x;
    for (int t = blockIdx.x * blockDim.x + threadIdx.x; t < num_quads; t += stride) {
        int4 i4 = __ldg(reinterpret_cast<const int4*>(idx_i) + t);
        int4 j4 = __ldg(reinterpret_cast<const int4*>(idx_j) + t);

        float4 a0 = fetch(sm, i4.x);
        float4 a1 = fetch(sm, i4.y);
        float4 a2 = fetch(sm, i4.z);
        float4 a3 = fetch(sm, i4.w);
        float4 b0 = fetch(sm, j4.x);
        float4 b1 = fetch(sm, j4.y);
        float4 b2 = fetch(sm, j4.z);
        float4 b3 = fetch(sm, j4.w);

        float dx0 = a0.x-b0.x, dy0 = a0.y-b0.y, dz0 = a0.z-b0.z;
        float dx1 = a1.x-b1.x, dy1 = a1.y-b1.y, dz1 = a1.z-b1.z;
        float dx2 = a2.x-b2.x, dy2 = a2.y-b2.y, dz2 = a2.z-b2.z;
        float dx3 = a3.x-b3.x, dy3 = a3.y-b3.y, dz3 = a3.z-b3.z;

        float4 o;
        o.x = sqrtf(fmaf(dx0, dx0, fmaf(dy0, dy0, dz0*dz0)));
        o.y = sqrtf(fmaf(dx1, dx1, fmaf(dy1, dy1, dz1*dz1)));
        o.z = sqrtf(fmaf(dx2, dx2, fmaf(dy2, dy2, dz2*dz2)));
        o.w = sqrtf(fmaf(dx3, dx3, fmaf(dy3, dy3, dz3*dz3)));

        reinterpret_cast<float4*>(out)[t] = o;
    }
}

// ---------- fallback: direct scalar gathers if N exceeds scratch ----------
__global__ __launch_bounds__(256) void pairwise_dist_direct_kernel(
    const float* __restrict__ R,
    const int*   __restrict__ idx_i,
    const int*   __restrict__ idx_j,
    float* __restrict__ out,
    int E)
{
    int e = blockIdx.x * blockDim.x + threadIdx.x;
    if (e >= E) return;
    int i = idx_i[e], j = idx_j[e];
    float dx = R[3*(size_t)i+0] - R[3*(size_t)j+0];
    float dy = R[3*(size_t)i+1] - R[3*(size_t)j+1];
    float dz = R[3*(size_t)i+2] - R[3*(size_t)j+2];
    out[e] = sqrtf(fmaf(dx, dx, fmaf(dy, dy, dz*dz)));
}

// ---------- scalar tail for E % 4 != 0 (defensive) ----------
__global__ void pairwise_dist_tail_kernel(
    const int* __restrict__ idx_i,
    const int* __restrict__ idx_j,
    float* __restrict__ out,
    int start, int E)
{
    int e = start + blockIdx.x * blockDim.x + threadIdx.x;
    if (e >= E) return;
    float4 a = g_R4[(unsigned)idx_i[e]];
    float4 b = g_R4[(unsigned)idx_j[e]];
    float dx = a.x-b.x, dy = a.y-b.y, dz = a.z-b.z;
    out[e] = sqrtf(fmaf(dx, dx, fmaf(dy, dy, dz*dz)));
}

extern "C" void kernel_launch(void* const* d_in, const int* in_sizes, int n_in,
                              void* d_out, int out_size)
{
    const float* R     = (const float*)d_in[0];
    const int*   idx_i = (const int*)d_in[1];
    const int*   idx_j = (const int*)d_in[2];
    float*       out   = (float*)d_out;

    int n_atoms = in_sizes[0] / 3;
    int E = in_sizes[1];

    if (n_atoms > R4_CAP) {
        int blocks = (E + 255) / 256;
        pairwise_dist_direct_kernel<<<blocks, 256>>>(R, idx_i, idx_j, out, E);
        return;
    }

    // Prologue: build padded float4 table.
    int n_groups = (n_atoms + 3) / 4;
    pad_R_kernel<<<(n_groups + 255) / 256, 256>>>(
        (const float4*)R, n_groups, n_atoms);

    // Main: persistent grid, 200 KB dynamic SMEM slice.
    static bool attr_set = false;
    const int smem_bytes = SMEM_ATOMS * (int)sizeof(float4);
    if (!attr_set) {
        cudaFuncSetAttribute(pairwise_dist_hybrid_kernel,
                             cudaFuncAttributeMaxDynamicSharedMemorySize,
                             smem_bytes);
        attr_set = true;
    }

    int num_quads = E >> 2;
    if (num_quads > 0)
        pairwise_dist_hybrid_kernel<<<148, 1024, smem_bytes>>>(
            idx_i, idx_j, out, num_quads);

    int tail = E & 3;
    if (tail)
        pairwise_dist_tail_kernel<<<1, 32>>>(idx_i, idx_j, out, E - tail, E);
}

// round 9
// speedup vs baseline: 1.7577x; 1.7577x over previous
#include <cuda_runtime.h>
#include <cuda_bf16.h>

// PairwiseDistances: d[e] = || R[idx_i[e]] - R[idx_j[e]] ||_2
// R: [N,3] f32 (N=100000); idx: int32 [E]; out: f32 [E]. E = 6,400,000.
//
// R6 evidence: main kernel is at the L1tex wavefront floor (2 gather
// wavefronts per edge, ~50.8us). R7 hybrid-SMEM regressed (predicated
// dual-path + L1 carveout + occupancy loss) — reverted. R8 keeps the R6
// main kernel and vectorizes the pad prologue (3.2us -> ~1us).

#define R4_CAP 131072  // padded table capacity (2 MB); N=100000 fits

__device__ float4 g_R4[R4_CAP];

// ---------- prologue: pad R[N,3] -> g_R4[N] (float4), vectorized ----------
// 4 atoms (48B = 3 float4 reads) per thread -> 4 float4 writes.
__global__ __launch_bounds__(256) void pad_R_kernel(
    const float4* __restrict__ R4in, int n_groups /* ceil(n/4) */, int n_atoms)
{
    int g = blockIdx.x * blockDim.x + threadIdx.x;
    if (g >= n_groups) return;
    int base = g * 4;
    if (base + 4 <= n_atoms) {
        float4 p0 = __ldg(R4in + 3*g + 0);   // x0 y0 z0 x1
        float4 p1 = __ldg(R4in + 3*g + 1);   // y1 z1 x2 y2
        float4 p2 = __ldg(R4in + 3*g + 2);   // z2 x3 y3 z3
        g_R4[base + 0] = make_float4(p0.x, p0.y, p0.z, 0.f);
        g_R4[base + 1] = make_float4(p0.w, p1.x, p1.y, 0.f);
        g_R4[base + 2] = make_float4(p1.z, p1.w, p2.x, 0.f);
        g_R4[base + 3] = make_float4(p2.y, p2.z, p2.w, 0.f);
    } else {
        const float* r = (const float*)R4in;
        for (int a = base; a < n_atoms; ++a)
            g_R4[a] = make_float4(r[3*a+0], r[3*a+1], r[3*a+2], 0.f);
    }
}

// One LDG.128 per gather: 1 L1tex wavefront + 1 L2 sector. evict_last keeps
// the 1.6 MB table preferentially L1/L2-resident against streaming traffic.
__device__ __forceinline__ float4 ldg_row(int idx)
{
    float4 v;
    const float4* p = g_R4 + (unsigned)idx;
    asm("ld.global.nc.L1::evict_last.v4.f32 {%0,%1,%2,%3}, [%4];"
        : "=f"(v.x), "=f"(v.y), "=f"(v.z), "=f"(v.w)
        : "l"(p));
    return v;
}

// ---------- main kernel (R6, at the wavefront floor) ----------
__global__ __launch_bounds__(256) void pairwise_dist_kernel(
    const int*   __restrict__ idx_i,
    const int*   __restrict__ idx_j,
    float* __restrict__ out,
    int num_quads)   // E/4
{
    int t = blockIdx.x * blockDim.x + threadIdx.x;
    if (t >= num_quads) return;

    // 16B vectorized index loads: 4 edges per thread.
    int4 i4 = __ldg(reinterpret_cast<const int4*>(idx_i) + t);
    int4 j4 = __ldg(reinterpret_cast<const int4*>(idx_j) + t);

    // 8 independent 16B gathers — high MLP, L2-resident table.
    float4 a0 = ldg_row(i4.x);
    float4 a1 = ldg_row(i4.y);
    float4 a2 = ldg_row(i4.z);
    float4 a3 = ldg_row(i4.w);
    float4 b0 = ldg_row(j4.x);
    float4 b1 = ldg_row(j4.y);
    float4 b2 = ldg_row(j4.z);
    float4 b3 = ldg_row(j4.w);

    float dx0 = a0.x-b0.x, dy0 = a0.y-b0.y, dz0 = a0.z-b0.z;
    float dx1 = a1.x-b1.x, dy1 = a1.y-b1.y, dz1 = a1.z-b1.z;
    float dx2 = a2.x-b2.x, dy2 = a2.y-b2.y, dz2 = a2.z-b2.z;
    float dx3 = a3.x-b3.x, dy3 = a3.y-b3.y, dz3 = a3.z-b3.z;

    float4 o;
    o.x = sqrtf(fmaf(dx0, dx0, fmaf(dy0, dy0, dz0*dz0)));
    o.y = sqrtf(fmaf(dx1, dx1, fmaf(dy1, dy1, dz1*dz1)));
    o.z = sqrtf(fmaf(dx2, dx2, fmaf(dy2, dy2, dz2*dz2)));
    o.w = sqrtf(fmaf(dx3, dx3, fmaf(dy3, dy3, dz3*dz3)));

    reinterpret_cast<float4*>(out)[t] = o;
}

// ---------- fallback: direct scalar gathers if N exceeds scratch ----------
__global__ __launch_bounds__(256) void pairwise_dist_direct_kernel(
    const float* __restrict__ R,
    const int*   __restrict__ idx_i,
    const int*   __restrict__ idx_j,
    float* __restrict__ out,
    int E)
{
    int e = blockIdx.x * blockDim.x + threadIdx.x;
    if (e >= E) return;
    int i = idx_i[e], j = idx_j[e];
    float dx = R[3*(size_t)i+0] - R[3*(size_t)j+0];
    float dy = R[3*(size_t)i+1] - R[3*(size_t)j+1];
    float dz = R[3*(size_t)i+2] - R[3*(size_t)j+2];
    out[e] = sqrtf(fmaf(dx, dx, fmaf(dy, dy, dz*dz)));
}

// ---------- scalar tail for E % 4 != 0 (defensive) ----------
__global__ void pairwise_dist_tail_kernel(
    const int* __restrict__ idx_i,
    const int* __restrict__ idx_j,
    float* __restrict__ out,
    int start, int E)
{
    int e = start + blockIdx.x * blockDim.x + threadIdx.x;
    if (e >= E) return;
    float4 a = g_R4[(unsigned)idx_i[e]];
    float4 b = g_R4[(unsigned)idx_j[e]];
    float dx = a.x-b.x, dy = a.y-b.y, dz = a.z-b.z;
    out[e] = sqrtf(fmaf(dx, dx, fmaf(dy, dy, dz*dz)));
}

extern "C" void kernel_launch(void* const* d_in, const int* in_sizes, int n_in,
                              void* d_out, int out_size)
{
    const float* R     = (const float*)d_in[0];
    const int*   idx_i = (const int*)d_in[1];
    const int*   idx_j = (const int*)d_in[2];
    float*       out   = (float*)d_out;

    int n_atoms = in_sizes[0] / 3;
    int E = in_sizes[1];

    if (n_atoms > R4_CAP) {
        int blocks = (E + 255) / 256;
        pairwise_dist_direct_kernel<<<blocks, 256>>>(R, idx_i, idx_j, out, E);
        return;
    }

    // Prologue: build padded float4 table (vectorized).
    int n_groups = (n_atoms + 3) / 4;
    pad_R_kernel<<<(n_groups + 255) / 256, 256>>>(
        (const float4*)R, n_groups, n_atoms);

    int num_quads = E >> 2;
    int blocks = (num_quads + 255) / 256;
    if (blocks > 0)
        pairwise_dist_kernel<<<blocks, 256>>>(idx_i, idx_j, out, num_quads);

    int tail = E & 3;
    if (tail)
        pairwise_dist_tail_kernel<<<1, 32>>>(idx_i, idx_j, out, E - tail, E);
}